// round 6
// baseline (speedup 1.0000x reference)
#include <cuda_runtime.h>
#include <math.h>
#include <stdint.h>

// ---------------------------------------------------------------------------
// CoPE, f32x2 FMA, half-warp row-split (broadcast LDS), 64-reg accumulators:
//   inv_n = 1/max(||pos_n||, eps)
//   logits = (q @ pos^T) * inv_n / sqrt(D); gates = softmax(logits)
//   out = (gates * inv_n) @ pos
// B=4, T=4096, D=4096, N=16.
// ---------------------------------------------------------------------------

typedef unsigned long long ull;

#define DIM        4096
#define DIM4       1024               // float4 per row
#define NPOS       16
#define ROWS_TOT   16384
#define ROWS_BLK   32                 // 8 warps x 4 rows (2 per half-warp)
#define NBLOCKS    (ROWS_TOT / ROWS_BLK)   // 512
#define NTHREADS   256
#define CHUNK_F4   128                // float4 of D per n-row per chunk
#define NCHUNKS    8

#define BUF_FLOATS (NPOS * CHUNK_F4 * 4)   // 8192 floats = 32KB per buffer
#define SMEM_BYTES (2 * BUF_FLOATS * 4)    // 64KB -> 2 CTAs/SM

__device__ float g_inv[NPOS];

// ---------------------------------------------------------------------------
__global__ void cope_inv_kernel(const float* __restrict__ pos)
{
    const int n   = blockIdx.x;
    const int tid = threadIdx.x;
    const float* row = pos + n * DIM;

    float s = 0.f;
    #pragma unroll 4
    for (int i = tid; i < DIM; i += 256) {
        float v = row[i];
        s = fmaf(v, v, s);
    }
    #pragma unroll
    for (int o = 16; o > 0; o >>= 1) s += __shfl_down_sync(0xffffffffu, s, o);

    __shared__ float sred[8];
    if ((tid & 31) == 0) sred[tid >> 5] = s;
    __syncthreads();
    if (tid == 0) {
        float t = 0.f;
        #pragma unroll
        for (int w = 0; w < 8; w++) t += sred[w];
        g_inv[n] = 1.0f / fmaxf(sqrtf(t), 1e-12f);
    }
}

// ---------------------------------------------------------------------------
__device__ __forceinline__ ull ffma2(ull a, ull b, ull c)
{
    ull d;
    asm("fma.rn.f32x2 %0, %1, %2, %3;" : "=l"(d) : "l"(a), "l"(b), "l"(c));
    return d;
}
__device__ __forceinline__ ull pack2(float lo, float hi)
{
    ull d;
    asm("mov.b64 %0, {%1, %2};" : "=l"(d) : "f"(lo), "f"(hi));
    return d;
}
__device__ __forceinline__ float lo2(ull a) { return __uint_as_float((unsigned)(a & 0xffffffffu)); }
__device__ __forceinline__ float hi2(ull a) { return __uint_as_float((unsigned)(a >> 32)); }

__device__ __forceinline__ void cp_async16(void* s, const void* g)
{
    uint32_t saddr = (uint32_t)__cvta_generic_to_shared(s);
    asm volatile("cp.async.cg.shared.global [%0], [%1], 16;\n"
                 :: "r"(saddr), "l"(g));
}
__device__ __forceinline__ void cp_commit()
{
    asm volatile("cp.async.commit_group;\n" ::);
}
__device__ __forceinline__ void cp_wait1()
{
    asm volatile("cp.async.wait_group 1;\n" ::);
}
__device__ __forceinline__ void cp_wait0()
{
    asm volatile("cp.async.wait_group 0;\n" ::);
}

// stage one [16][512]-float chunk of raw pos (async); 8 float4 per thread
__device__ __forceinline__ void stage_chunk(float4* buf, const float4* gp4,
                                            int c, int tid)
{
    #pragma unroll
    for (int i = 0; i < 8; i++) {
        int idx = tid + i * NTHREADS;        // 0..2047
        int n   = idx >> 7;                  // /128
        int d4  = idx & 127;
        cp_async16(buf + n * CHUNK_F4 + d4,
                   gp4 + (size_t)n * DIM4 + (size_t)c * CHUNK_F4 + d4);
    }
}

// ---------------------------------------------------------------------------
__global__ void __launch_bounds__(NTHREADS, 2)
cope_main_kernel(const float* __restrict__ q, const float* __restrict__ pos,
                 float* __restrict__ out)
{
    extern __shared__ float smem[];
    float4* buf0 = (float4*)smem;
    float4* buf1 = (float4*)(smem + BUF_FLOATS);

    const int tid  = threadIdx.x;
    const int wid  = tid >> 5;               // 0..7
    const int lane = tid & 31;
    const int h    = lane >> 4;              // half-warp id (row pair select)
    const int hl   = lane & 15;              // lane within half
    const int rowb = blockIdx.x * ROWS_BLK + wid * 4 + h * 2;

    const ulonglong2* qq  = (const ulonglong2*)q;
    const float4*     gp4 = (const float4*)pos;
    ulonglong2*       oo  = (ulonglong2*)out;

    // prologue: stage chunks 0,1
    stage_chunk(buf0, gp4, 0, tid); cp_commit();
    stage_chunk(buf1, gp4, 1, tid); cp_commit();

    // ------------------------- pass 1: logits ----------------------------
    // acc[r][n] : f32x2 partial dot over this thread's d-slice, rows rowb+r
    ull acc[2][16];
    #pragma unroll
    for (int r = 0; r < 2; r++)
        #pragma unroll
        for (int n = 0; n < NPOS; n++) acc[r][n] = 0ull;

    for (int c = 0; c < NCHUNKS; c++) {
        if (c < NCHUNKS - 1) cp_wait1(); else cp_wait0();
        __syncthreads();

        const ulonglong2* sp = (const ulonglong2*)((c & 1) ? buf1 : buf0);

        #pragma unroll 4
        for (int j = 0; j < 8; j++) {
            const int d4 = hl + j * 16;      // both halves: same smem addrs
            ulonglong2 q0 = qq[(size_t)(rowb + 0) * DIM4 + (size_t)c * CHUNK_F4 + d4];
            ulonglong2 q1 = qq[(size_t)(rowb + 1) * DIM4 + (size_t)c * CHUNK_F4 + d4];

            #pragma unroll
            for (int n = 0; n < NPOS; n++) {
                const ulonglong2 p = sp[n * CHUNK_F4 + d4];
                acc[0][n] = ffma2(q0.x, p.x, acc[0][n]);
                acc[0][n] = ffma2(q0.y, p.y, acc[0][n]);
                acc[1][n] = ffma2(q1.x, p.x, acc[1][n]);
                acc[1][n] = ffma2(q1.y, p.y, acc[1][n]);
            }
        }
        __syncthreads();
        if (c + 2 < NCHUNKS) {
            stage_chunk((c & 1) ? buf1 : buf0, gp4, c + 2, tid);
            cp_commit();
        }
    }
    // buffers now hold: buf0 = chunk 6, buf1 = chunk 7

    // ---- half-warp butterfly transpose-reduce over the 16 d-lanes --------
    // elements e = r*16+n (e<32); after 4 halving steps lane hl holds:
    //   w[0] = dot(row rowb+0, n=hl),  w[1] = dot(row rowb+1, n=hl)
    float w[32];
    #pragma unroll
    for (int r = 0; r < 2; r++)
        #pragma unroll
        for (int n = 0; n < NPOS; n++)
            w[r * 16 + n] = lo2(acc[r][n]) + hi2(acc[r][n]);

#define RED_STEP(m, L)                                              \
    _Pragma("unroll")                                               \
    for (int t = 0; t < (L); t++) {                                 \
        float a_  = w[2 * t], b_ = w[2 * t + 1];                    \
        float ao_ = __shfl_xor_sync(0xffffffffu, a_, (m));          \
        float bo_ = __shfl_xor_sync(0xffffffffu, b_, (m));          \
        w[t] = (hl & (m)) ? (b_ + bo_) : (a_ + ao_);                \
    }
    RED_STEP(1, 16)
    RED_STEP(2, 8)
    RED_STEP(4, 4)
    RED_STEP(8, 2)
#undef RED_STEP

    const float invn = __ldg(&g_inv[hl]);    // hl == code index n
    float lg0 = w[0] * 0.015625f * invn;     // row rowb+0
    float lg1 = w[1] * 0.015625f * invn;     // row rowb+1

    // ---- softmax over the 16 codes, entirely within each half-warp -------
    float m0 = lg0, m1 = lg1;
    #pragma unroll
    for (int o = 8; o > 0; o >>= 1) {
        m0 = fmaxf(m0, __shfl_xor_sync(0xffffffffu, m0, o));
        m1 = fmaxf(m1, __shfl_xor_sync(0xffffffffu, m1, o));
    }
    float e0 = expf(lg0 - m0), e1 = expf(lg1 - m1);
    float s0 = e0, s1 = e1;
    #pragma unroll
    for (int o = 8; o > 0; o >>= 1) {
        s0 += __shfl_xor_sync(0xffffffffu, s0, o);
        s1 += __shfl_xor_sync(0xffffffffu, s1, o);
    }
    const float g0 = e0 * (1.0f / s0) * invn;   // fold inv_norm into gate
    const float g1 = e1 * (1.0f / s1) * invn;

    // gather this half's gates, duplicated for f32x2
    ull gt[2][16];
    #pragma unroll
    for (int n = 0; n < NPOS; n++) {
        const int src = (lane & 16) | n;        // stay within own half
        float f0 = __shfl_sync(0xffffffffu, g0, src);
        float f1 = __shfl_sync(0xffffffffu, g1, src);
        gt[0][n] = pack2(f0, f0);
        gt[1][n] = pack2(f1, f1);
    }

    // -------------------------- pass 2: output ---------------------------
    // reverse chunk order: chunks 7 (buf1) and 6 (buf0) already resident
    for (int cc = 0; cc < NCHUNKS; cc++) {
        const int c = NCHUNKS - 1 - cc;
        if (c <= NCHUNKS - 3) {
            if (c > 0) cp_wait1(); else cp_wait0();
        }
        __syncthreads();

        const ulonglong2* sp = (const ulonglong2*)((c & 1) ? buf1 : buf0);

        #pragma unroll 4
        for (int j = 0; j < 8; j++) {
            const int d4 = hl + j * 16;
            ulonglong2 o0, o1;
            o0.x = o0.y = o1.x = o1.y = 0ull;

            #pragma unroll
            for (int n = 0; n < NPOS; n++) {
                const ulonglong2 p = sp[n * CHUNK_F4 + d4];
                o0.x = ffma2(gt[0][n], p.x, o0.x);
                o0.y = ffma2(gt[0][n], p.y, o0.y);
                o1.x = ffma2(gt[1][n], p.x, o1.x);
                o1.y = ffma2(gt[1][n], p.y, o1.y);
            }
            oo[(size_t)(rowb + 0) * DIM4 + (size_t)c * CHUNK_F4 + d4] = o0;
            oo[(size_t)(rowb + 1) * DIM4 + (size_t)c * CHUNK_F4 + d4] = o1;
        }
        __syncthreads();
        if (c >= 2) {
            stage_chunk((c & 1) ? buf1 : buf0, gp4, c - 2, tid);
            cp_commit();
        }
    }
}

// ---------------------------------------------------------------------------
extern "C" void kernel_launch(void* const* d_in, const int* in_sizes, int n_in,
                              void* d_out, int out_size)
{
    const float* q   = (const float*)d_in[0];
    // d_in[1] = x : unused by the reference computation
    const float* pos = (const float*)d_in[2];
    float* out = (float*)d_out;

    cudaFuncSetAttribute(cope_main_kernel,
                         cudaFuncAttributeMaxDynamicSharedMemorySize, SMEM_BYTES);

    cope_inv_kernel<<<NPOS, 256>>>(pos);
    cope_main_kernel<<<NBLOCKS, NTHREADS, SMEM_BYTES>>>(q, pos, out);
}

// round 7
// speedup vs baseline: 1.1414x; 1.1414x over previous
#include <cuda_runtime.h>
#include <math.h>
#include <stdint.h>

// ---------------------------------------------------------------------------
// CoPE, f32x2 FMA, half-warp N-SPLIT (4 rows/thread, 64-reg accumulators):
//   inv_n = 1/max(||pos_n||, eps)
//   logits = (q @ pos^T) * inv_n / sqrt(D); gates = softmax(logits)
//   out = (gates * inv_n) @ pos
// B=4, T=4096, D=4096, N=16.
// ---------------------------------------------------------------------------

typedef unsigned long long ull;

#define DIM        4096
#define DIM4       1024               // float4 per row
#define NPOS       16
#define ROWS_TOT   16384
#define ROWS_BLK   32                 // 8 warps x 4 rows
#define NBLOCKS    (ROWS_TOT / ROWS_BLK)   // 512
#define NTHREADS   256
#define CHUNK_F4   128                // float4 of D per n-row per chunk
#define NCHUNKS    8

#define BUF_FLOATS (NPOS * CHUNK_F4 * 4)   // 8192 floats = 32KB per buffer
#define SMEM_BYTES (2 * BUF_FLOATS * 4)    // 64KB -> 2 CTAs/SM

__device__ float g_inv[NPOS];

// ---------------------------------------------------------------------------
__global__ void cope_inv_kernel(const float* __restrict__ pos)
{
    const int n   = blockIdx.x;
    const int tid = threadIdx.x;
    const float* row = pos + n * DIM;

    float s = 0.f;
    #pragma unroll 4
    for (int i = tid; i < DIM; i += 256) {
        float v = row[i];
        s = fmaf(v, v, s);
    }
    #pragma unroll
    for (int o = 16; o > 0; o >>= 1) s += __shfl_down_sync(0xffffffffu, s, o);

    __shared__ float sred[8];
    if ((tid & 31) == 0) sred[tid >> 5] = s;
    __syncthreads();
    if (tid == 0) {
        float t = 0.f;
        #pragma unroll
        for (int w = 0; w < 8; w++) t += sred[w];
        g_inv[n] = 1.0f / fmaxf(sqrtf(t), 1e-12f);
    }
}

// ---------------------------------------------------------------------------
__device__ __forceinline__ ull ffma2(ull a, ull b, ull c)
{
    ull d;
    asm("fma.rn.f32x2 %0, %1, %2, %3;" : "=l"(d) : "l"(a), "l"(b), "l"(c));
    return d;
}
__device__ __forceinline__ ull add2(ull a, ull b)
{
    ull d;
    asm("add.rn.f32x2 %0, %1, %2;" : "=l"(d) : "l"(a), "l"(b));
    return d;
}
__device__ __forceinline__ ull pack2(float lo, float hi)
{
    ull d;
    asm("mov.b64 %0, {%1, %2};" : "=l"(d) : "f"(lo), "f"(hi));
    return d;
}
__device__ __forceinline__ float lo2(ull a) { return __uint_as_float((unsigned)(a & 0xffffffffu)); }
__device__ __forceinline__ float hi2(ull a) { return __uint_as_float((unsigned)(a >> 32)); }

__device__ __forceinline__ void cp_async16(void* s, const void* g)
{
    uint32_t saddr = (uint32_t)__cvta_generic_to_shared(s);
    asm volatile("cp.async.cg.shared.global [%0], [%1], 16;\n"
                 :: "r"(saddr), "l"(g));
}
__device__ __forceinline__ void cp_commit()
{
    asm volatile("cp.async.commit_group;\n" ::);
}
__device__ __forceinline__ void cp_wait1()
{
    asm volatile("cp.async.wait_group 1;\n" ::);
}
__device__ __forceinline__ void cp_wait0()
{
    asm volatile("cp.async.wait_group 0;\n" ::);
}

// stage one [16][512]-float chunk of raw pos (async); 8 float4 per thread
__device__ __forceinline__ void stage_chunk(float4* buf, const float4* gp4,
                                            int c, int tid)
{
    #pragma unroll
    for (int i = 0; i < 8; i++) {
        int idx = tid + i * NTHREADS;        // 0..2047
        int n   = idx >> 7;                  // /128
        int d4  = idx & 127;
        cp_async16(buf + n * CHUNK_F4 + d4,
                   gp4 + (size_t)n * DIM4 + (size_t)c * CHUNK_F4 + d4);
    }
}

// ---------------------------------------------------------------------------
__global__ void __launch_bounds__(NTHREADS, 2)
cope_main_kernel(const float* __restrict__ q, const float* __restrict__ pos,
                 float* __restrict__ out)
{
    extern __shared__ float smem[];
    float4* buf0 = (float4*)smem;
    float4* buf1 = (float4*)(smem + BUF_FLOATS);

    const int tid  = threadIdx.x;
    const int wid  = tid >> 5;               // 0..7
    const int lane = tid & 31;
    const int h    = lane >> 4;              // n-half: codes [8h, 8h+8)
    const int hl   = lane & 15;              // d-slice within half
    const int rowb = blockIdx.x * ROWS_BLK + wid * 4;   // warp's 4 rows

    const ulonglong2* qq  = (const ulonglong2*)q;
    const float4*     gp4 = (const float4*)pos;
    ulonglong2*       oo  = (ulonglong2*)out;

    // prologue: stage chunks 0,1
    stage_chunk(buf0, gp4, 0, tid); cp_commit();
    stage_chunk(buf1, gp4, 1, tid); cp_commit();

    // ------------------------- pass 1: logits ----------------------------
    // acc[r][nn] : f32x2 partial dot, row rowb+r, code n = 8h+nn,
    //              over d-slice {hl + j*16}
    ull acc[4][8];
    #pragma unroll
    for (int r = 0; r < 4; r++)
        #pragma unroll
        for (int nn = 0; nn < 8; nn++) acc[r][nn] = 0ull;

    for (int c = 0; c < NCHUNKS; c++) {
        if (c < NCHUNKS - 1) cp_wait1(); else cp_wait0();
        __syncthreads();

        const ulonglong2* sp = (const ulonglong2*)((c & 1) ? buf1 : buf0);
        const ulonglong2* sph = sp + h * 8 * CHUNK_F4;   // my n-half

        #pragma unroll
        for (int j = 0; j < 8; j++) {
            const int d4 = hl + j * 16;      // same for both halves
            ulonglong2 qv[4];
            #pragma unroll
            for (int r = 0; r < 4; r++)
                qv[r] = qq[(size_t)(rowb + r) * DIM4 + (size_t)c * CHUNK_F4 + d4];

            #pragma unroll
            for (int nn = 0; nn < 8; nn++) {
                const ulonglong2 p = sph[nn * CHUNK_F4 + d4];
                #pragma unroll
                for (int r = 0; r < 4; r++) {
                    ull a = acc[r][nn];
                    a = ffma2(qv[r].x, p.x, a);
                    a = ffma2(qv[r].y, p.y, a);
                    acc[r][nn] = a;
                }
            }
        }
        __syncthreads();
        if (c + 2 < NCHUNKS) {
            stage_chunk((c & 1) ? buf1 : buf0, gp4, c + 2, tid);
            cp_commit();
        }
    }
    // buffers now hold: buf0 = chunk 6, buf1 = chunk 7

    // ---- half-warp butterfly transpose-reduce over the 16 d-lanes --------
    // elem e: r = 2*(e>>4) + ((e>>3)&1), nn = e&7.  After 4 steps, lane hl
    // slot s holds dot(row rowb + 2s + ((hl>>3)&1), n = 8h + (hl&7)).
    float w[32];
    #pragma unroll
    for (int e = 0; e < 32; e++) {
        const int r  = 2 * (e >> 4) + ((e >> 3) & 1);
        const int nn = e & 7;
        w[e] = lo2(acc[r][nn]) + hi2(acc[r][nn]);
    }

#define RED_STEP(m, L)                                              \
    _Pragma("unroll")                                               \
    for (int t = 0; t < (L); t++) {                                 \
        float a_  = w[2 * t], b_ = w[2 * t + 1];                    \
        float ao_ = __shfl_xor_sync(0xffffffffu, a_, (m));          \
        float bo_ = __shfl_xor_sync(0xffffffffu, b_, (m));          \
        w[t] = (hl & (m)) ? (b_ + bo_) : (a_ + ao_);                \
    }
    RED_STEP(1, 16)
    RED_STEP(2, 8)
    RED_STEP(4, 4)
    RED_STEP(8, 2)
#undef RED_STEP

    // this lane's code index: n = (lane>>4)*8 + (lane&7)
    const int  nidx = ((lane & 16) >> 1) | (lane & 7);
    const float invn = __ldg(&g_inv[nidx]);
    float lg0 = w[0] * 0.015625f * invn;     // row rowb + 0 + ((hl>>3)&1)... slot0
    float lg1 = w[1] * 0.015625f * invn;     // slot1: rows +2

    // ---- softmax over 16 codes: lane group = xor-closure of {1,2,4,16} ---
    float m0 = lg0, m1 = lg1;
    #pragma unroll
    for (int k = 0; k < 4; k++) {
        const int msk = (k < 3) ? (1 << k) : 16;
        m0 = fmaxf(m0, __shfl_xor_sync(0xffffffffu, m0, msk));
        m1 = fmaxf(m1, __shfl_xor_sync(0xffffffffu, m1, msk));
    }
    float e0 = expf(lg0 - m0), e1 = expf(lg1 - m1);
    float s0 = e0, s1 = e1;
    #pragma unroll
    for (int k = 0; k < 4; k++) {
        const int msk = (k < 3) ? (1 << k) : 16;
        s0 += __shfl_xor_sync(0xffffffffu, s0, msk);
        s1 += __shfl_xor_sync(0xffffffffu, s1, msk);
    }
    const float g0 = e0 * (1.0f / s0) * invn;   // fold inv_norm into gate
    const float g1 = e1 * (1.0f / s1) * invn;

    // gather gates for my 4 rows x my 8 codes, duplicated for f32x2.
    // gate(row rowb+r, n=8h+nn) lives at lane (lane&16)|((r&1)<<3)|nn,
    // slot r>>1.
    ull gt[4][8];
    #pragma unroll
    for (int r = 0; r < 4; r++)
        #pragma unroll
        for (int nn = 0; nn < 8; nn++) {
            const int src = (lane & 16) | ((r & 1) << 3) | nn;
            float gv = __shfl_sync(0xffffffffu, (r < 2) ? g0 : g1, src);
            gt[r][nn] = pack2(gv, gv);
        }

    // -------------------------- pass 2: output ---------------------------
    // reverse chunk order: chunks 7 (buf1) and 6 (buf0) already resident
    for (int cc = 0; cc < NCHUNKS; cc++) {
        const int c = NCHUNKS - 1 - cc;
        if (c <= NCHUNKS - 3) {
            if (c > 0) cp_wait1(); else cp_wait0();
        }
        __syncthreads();

        const ulonglong2* sp = (const ulonglong2*)((c & 1) ? buf1 : buf0);
        const ulonglong2* sph = sp + h * 8 * CHUNK_F4;

        #pragma unroll
        for (int j = 0; j < 8; j++) {
            const int d4 = hl + j * 16;
            ulonglong2 o[4];
            #pragma unroll
            for (int r = 0; r < 4; r++) { o[r].x = 0ull; o[r].y = 0ull; }

            #pragma unroll
            for (int nn = 0; nn < 8; nn++) {
                const ulonglong2 p = sph[nn * CHUNK_F4 + d4];
                #pragma unroll
                for (int r = 0; r < 4; r++) {
                    o[r].x = ffma2(gt[r][nn], p.x, o[r].x);
                    o[r].y = ffma2(gt[r][nn], p.y, o[r].y);
                }
            }

            // cross-half combine: my stored rows are rowb+2h, rowb+2h+1.
            // send my partials of the PARTNER's rows; receive partner's
            // partials of MY rows.
            ull sx0 = h ? o[0].x : o[2].x,  sy0 = h ? o[0].y : o[2].y;
            ull sx1 = h ? o[1].x : o[3].x,  sy1 = h ? o[1].y : o[3].y;
            ull rx0 = __shfl_xor_sync(0xffffffffu, sx0, 16);
            ull ry0 = __shfl_xor_sync(0xffffffffu, sy0, 16);
            ull rx1 = __shfl_xor_sync(0xffffffffu, sx1, 16);
            ull ry1 = __shfl_xor_sync(0xffffffffu, sy1, 16);

            ulonglong2 t0, t1;
            t0.x = add2(h ? o[2].x : o[0].x, rx0);
            t0.y = add2(h ? o[2].y : o[0].y, ry0);
            t1.x = add2(h ? o[3].x : o[1].x, rx1);
            t1.y = add2(h ? o[3].y : o[1].y, ry1);

            const size_t rs = (size_t)(rowb + 2 * h);
            oo[rs * DIM4 + (size_t)c * CHUNK_F4 + d4] = t0;
            oo[(rs + 1) * DIM4 + (size_t)c * CHUNK_F4 + d4] = t1;
        }
        __syncthreads();
        if (c >= 2) {
            stage_chunk((c & 1) ? buf1 : buf0, gp4, c - 2, tid);
            cp_commit();
        }
    }
}

// ---------------------------------------------------------------------------
extern "C" void kernel_launch(void* const* d_in, const int* in_sizes, int n_in,
                              void* d_out, int out_size)
{
    const float* q   = (const float*)d_in[0];
    // d_in[1] = x : unused by the reference computation
    const float* pos = (const float*)d_in[2];
    float* out = (float*)d_out;

    cudaFuncSetAttribute(cope_main_kernel,
                         cudaFuncAttributeMaxDynamicSharedMemorySize, SMEM_BYTES);

    cope_inv_kernel<<<NPOS, 256>>>(pos);
    cope_main_kernel<<<NBLOCKS, NTHREADS, SMEM_BYTES>>>(q, pos, out);
}

// round 8
// speedup vs baseline: 1.4288x; 1.2517x over previous
#include <cuda_runtime.h>
#include <math.h>
#include <stdint.h>

// ---------------------------------------------------------------------------
// CoPE, f32x2 FMA, half-warp n-split, q AND pos staged via cp.async:
//   inv_n = 1/max(||pos_n||, eps)
//   logits = (q @ pos^T) * inv_n / sqrt(D); gates = softmax(logits)
//   out = (gates * inv_n) @ pos
// B=4, T=4096, D=4096, N=16.
// ---------------------------------------------------------------------------

typedef unsigned long long ull;

#define DIM        4096
#define DIM4       1024               // float4 per row
#define NPOS       16
#define ROWS_TOT   16384
#define ROWS_BLK   32                 // 8 warps x 4 rows
#define NBLOCKS    (ROWS_TOT / ROWS_BLK)   // 512
#define NTHREADS   256
#define CHUNK_F4   64                 // float4 of D per row per chunk
#define NCHUNKS    16

#define POS_BUF_F4 (NPOS * CHUNK_F4)       // 1024 float4 = 16KB
#define Q_BUF_F4   (ROWS_BLK * CHUNK_F4)   // 2048 float4 = 32KB
#define SMEM_BYTES ((2 * POS_BUF_F4 + 2 * Q_BUF_F4) * 16)   // 96KB -> 2 CTAs/SM

__device__ float g_inv[NPOS];

// ---------------------------------------------------------------------------
__global__ void cope_inv_kernel(const float* __restrict__ pos)
{
    const int n   = blockIdx.x;
    const int tid = threadIdx.x;
    const float* row = pos + n * DIM;

    float s = 0.f;
    #pragma unroll 4
    for (int i = tid; i < DIM; i += 256) {
        float v = row[i];
        s = fmaf(v, v, s);
    }
    #pragma unroll
    for (int o = 16; o > 0; o >>= 1) s += __shfl_down_sync(0xffffffffu, s, o);

    __shared__ float sred[8];
    if ((tid & 31) == 0) sred[tid >> 5] = s;
    __syncthreads();
    if (tid == 0) {
        float t = 0.f;
        #pragma unroll
        for (int w = 0; w < 8; w++) t += sred[w];
        g_inv[n] = 1.0f / fmaxf(sqrtf(t), 1e-12f);
    }
}

// ---------------------------------------------------------------------------
__device__ __forceinline__ ull ffma2(ull a, ull b, ull c)
{
    ull d;
    asm("fma.rn.f32x2 %0, %1, %2, %3;" : "=l"(d) : "l"(a), "l"(b), "l"(c));
    return d;
}
__device__ __forceinline__ ull add2(ull a, ull b)
{
    ull d;
    asm("add.rn.f32x2 %0, %1, %2;" : "=l"(d) : "l"(a), "l"(b));
    return d;
}
__device__ __forceinline__ ull pack2(float lo, float hi)
{
    ull d;
    asm("mov.b64 %0, {%1, %2};" : "=l"(d) : "f"(lo), "f"(hi));
    return d;
}
__device__ __forceinline__ float lo2(ull a) { return __uint_as_float((unsigned)(a & 0xffffffffu)); }
__device__ __forceinline__ float hi2(ull a) { return __uint_as_float((unsigned)(a >> 32)); }

__device__ __forceinline__ void cp_async16(void* s, const void* g)
{
    uint32_t saddr = (uint32_t)__cvta_generic_to_shared(s);
    asm volatile("cp.async.cg.shared.global [%0], [%1], 16;\n"
                 :: "r"(saddr), "l"(g));
}
__device__ __forceinline__ void cp_commit()
{
    asm volatile("cp.async.commit_group;\n" ::);
}
__device__ __forceinline__ void cp_wait1()
{
    asm volatile("cp.async.wait_group 1;\n" ::);
}
__device__ __forceinline__ void cp_wait0()
{
    asm volatile("cp.async.wait_group 0;\n" ::);
}

// stage [16][256]-float pos chunk (4 cp.async / thread)
__device__ __forceinline__ void stage_pos(float4* buf, const float4* gp4,
                                          int c, int tid)
{
    #pragma unroll
    for (int i = 0; i < 4; i++) {
        int idx = tid + i * NTHREADS;        // 0..1023
        int n   = idx >> 6;
        int d4  = idx & 63;
        cp_async16(buf + idx,
                   gp4 + (size_t)n * DIM4 + (size_t)c * CHUNK_F4 + d4);
    }
}

// stage [32][256]-float q chunk (8 cp.async / thread)
__device__ __forceinline__ void stage_q(float4* buf, const float4* q4,
                                        int rowB0, int c, int tid)
{
    #pragma unroll
    for (int i = 0; i < 8; i++) {
        int idx = tid + i * NTHREADS;        // 0..2047
        int r   = idx >> 6;
        int d4  = idx & 63;
        cp_async16(buf + idx,
                   q4 + (size_t)(rowB0 + r) * DIM4 + (size_t)c * CHUNK_F4 + d4);
    }
}

// ---------------------------------------------------------------------------
__global__ void __launch_bounds__(NTHREADS, 2)
cope_main_kernel(const float* __restrict__ q, const float* __restrict__ pos,
                 float* __restrict__ out)
{
    extern __shared__ float4 smem4[];
    float4* pos0 = smem4;
    float4* pos1 = smem4 + POS_BUF_F4;
    float4* qb0  = smem4 + 2 * POS_BUF_F4;
    float4* qb1  = qb0 + Q_BUF_F4;

    const int tid   = threadIdx.x;
    const int wid   = tid >> 5;              // 0..7
    const int lane  = tid & 31;
    const int h     = lane >> 4;             // n-half: codes [8h, 8h+8)
    const int hl    = lane & 15;             // d-slice within half
    const int rowB0 = blockIdx.x * ROWS_BLK;
    const int rowb  = rowB0 + wid * 4;       // this warp's 4 rows

    const float4* q4  = (const float4*)q;
    const float4* gp4 = (const float4*)pos;
    ulonglong2*   oo  = (ulonglong2*)out;

    // prologue: stage chunks 0,1 (pos+q together per group)
    stage_pos(pos0, gp4, 0, tid); stage_q(qb0, q4, rowB0, 0, tid); cp_commit();
    stage_pos(pos1, gp4, 1, tid); stage_q(qb1, q4, rowB0, 1, tid); cp_commit();

    // ------------------------- pass 1: logits ----------------------------
    ull acc[4][8];
    #pragma unroll
    for (int r = 0; r < 4; r++)
        #pragma unroll
        for (int nn = 0; nn < 8; nn++) acc[r][nn] = 0ull;

    for (int c = 0; c < NCHUNKS; c++) {
        if (c < NCHUNKS - 1) cp_wait1(); else cp_wait0();
        __syncthreads();

        const ulonglong2* sp  = (const ulonglong2*)((c & 1) ? pos1 : pos0);
        const ulonglong2* sq  = (const ulonglong2*)((c & 1) ? qb1  : qb0);
        const ulonglong2* sph = sp + h * 8 * CHUNK_F4;

        #pragma unroll
        for (int j = 0; j < 4; j++) {
            const int d4 = hl + j * 16;
            ulonglong2 qv[4];
            #pragma unroll
            for (int r = 0; r < 4; r++)
                qv[r] = sq[(wid * 4 + r) * CHUNK_F4 + d4];

            #pragma unroll
            for (int nn = 0; nn < 8; nn++) {
                const ulonglong2 p = sph[nn * CHUNK_F4 + d4];
                #pragma unroll
                for (int r = 0; r < 4; r++) {
                    ull a = acc[r][nn];
                    a = ffma2(qv[r].x, p.x, a);
                    a = ffma2(qv[r].y, p.y, a);
                    acc[r][nn] = a;
                }
            }
        }
        __syncthreads();
        if (c + 2 < NCHUNKS) {
            float4* pb = (c & 1) ? pos1 : pos0;
            float4* qb = (c & 1) ? qb1  : qb0;
            stage_pos(pb, gp4, c + 2, tid);
            stage_q(qb, q4, rowB0, c + 2, tid);
            cp_commit();
        }
    }
    // pos buffers now hold: pos0 = chunk 14, pos1 = chunk 15

    // ---- half-warp butterfly transpose-reduce over the 16 d-lanes --------
    float w[32];
    #pragma unroll
    for (int e = 0; e < 32; e++) {
        const int r  = 2 * (e >> 4) + ((e >> 3) & 1);
        const int nn = e & 7;
        w[e] = lo2(acc[r][nn]) + hi2(acc[r][nn]);
    }

#define RED_STEP(m, L)                                              \
    _Pragma("unroll")                                               \
    for (int t = 0; t < (L); t++) {                                 \
        float a_  = w[2 * t], b_ = w[2 * t + 1];                    \
        float ao_ = __shfl_xor_sync(0xffffffffu, a_, (m));          \
        float bo_ = __shfl_xor_sync(0xffffffffu, b_, (m));          \
        w[t] = (hl & (m)) ? (b_ + bo_) : (a_ + ao_);                \
    }
    RED_STEP(1, 16)
    RED_STEP(2, 8)
    RED_STEP(4, 4)
    RED_STEP(8, 2)
#undef RED_STEP

    const int  nidx = ((lane & 16) >> 1) | (lane & 7);
    const float invn = __ldg(&g_inv[nidx]);
    float lg0 = w[0] * 0.015625f * invn;
    float lg1 = w[1] * 0.015625f * invn;

    // ---- softmax over 16 codes: lane group = xor-closure of {1,2,4,16} ---
    float m0 = lg0, m1 = lg1;
    #pragma unroll
    for (int k = 0; k < 4; k++) {
        const int msk = (k < 3) ? (1 << k) : 16;
        m0 = fmaxf(m0, __shfl_xor_sync(0xffffffffu, m0, msk));
        m1 = fmaxf(m1, __shfl_xor_sync(0xffffffffu, m1, msk));
    }
    float e0 = expf(lg0 - m0), e1 = expf(lg1 - m1);
    float s0 = e0, s1 = e1;
    #pragma unroll
    for (int k = 0; k < 4; k++) {
        const int msk = (k < 3) ? (1 << k) : 16;
        s0 += __shfl_xor_sync(0xffffffffu, s0, msk);
        s1 += __shfl_xor_sync(0xffffffffu, s1, msk);
    }
    const float g0 = e0 * (1.0f / s0) * invn;
    const float g1 = e1 * (1.0f / s1) * invn;

    // gather gates for my 4 rows x my 8 codes, duplicated for f32x2
    ull gt[4][8];
    #pragma unroll
    for (int r = 0; r < 4; r++)
        #pragma unroll
        for (int nn = 0; nn < 8; nn++) {
            const int src = (lane & 16) | ((r & 1) << 3) | nn;
            float gv = __shfl_sync(0xffffffffu, (r < 2) ? g0 : g1, src);
            gt[r][nn] = pack2(gv, gv);
        }

    // -------------------------- pass 2: output ---------------------------
    // reverse chunk order: chunks 15 (pos1) and 14 (pos0) already resident
    for (int cc = 0; cc < NCHUNKS; cc++) {
        const int c = NCHUNKS - 1 - cc;
        if (c <= NCHUNKS - 3) {
            if (c > 0) cp_wait1(); else cp_wait0();
        }
        __syncthreads();

        const ulonglong2* sp  = (const ulonglong2*)((c & 1) ? pos1 : pos0);
        const ulonglong2* sph = sp + h * 8 * CHUNK_F4;

        #pragma unroll
        for (int j = 0; j < 4; j++) {
            const int d4 = hl + j * 16;
            ulonglong2 o[4];
            #pragma unroll
            for (int r = 0; r < 4; r++) { o[r].x = 0ull; o[r].y = 0ull; }

            #pragma unroll
            for (int nn = 0; nn < 8; nn++) {
                const ulonglong2 p = sph[nn * CHUNK_F4 + d4];
                #pragma unroll
                for (int r = 0; r < 4; r++) {
                    o[r].x = ffma2(gt[r][nn], p.x, o[r].x);
                    o[r].y = ffma2(gt[r][nn], p.y, o[r].y);
                }
            }

            // cross-half combine: my stored rows are rowb+2h, rowb+2h+1
            ull sx0 = h ? o[0].x : o[2].x,  sy0 = h ? o[0].y : o[2].y;
            ull sx1 = h ? o[1].x : o[3].x,  sy1 = h ? o[1].y : o[3].y;
            ull rx0 = __shfl_xor_sync(0xffffffffu, sx0, 16);
            ull ry0 = __shfl_xor_sync(0xffffffffu, sy0, 16);
            ull rx1 = __shfl_xor_sync(0xffffffffu, sx1, 16);
            ull ry1 = __shfl_xor_sync(0xffffffffu, sy1, 16);

            ulonglong2 t0, t1;
            t0.x = add2(h ? o[2].x : o[0].x, rx0);
            t0.y = add2(h ? o[2].y : o[0].y, ry0);
            t1.x = add2(h ? o[3].x : o[1].x, rx1);
            t1.y = add2(h ? o[3].y : o[1].y, ry1);

            const size_t rs = (size_t)(rowb + 2 * h);
            oo[rs * DIM4 + (size_t)c * CHUNK_F4 + d4] = t0;
            oo[(rs + 1) * DIM4 + (size_t)c * CHUNK_F4 + d4] = t1;
        }
        __syncthreads();
        if (c >= 2) {
            stage_pos((c & 1) ? pos1 : pos0, gp4, c - 2, tid);
            cp_commit();
        }
    }
}

// ---------------------------------------------------------------------------
extern "C" void kernel_launch(void* const* d_in, const int* in_sizes, int n_in,
                              void* d_out, int out_size)
{
    const float* q   = (const float*)d_in[0];
    // d_in[1] = x : unused by the reference computation
    const float* pos = (const float*)d_in[2];
    float* out = (float*)d_out;

    cudaFuncSetAttribute(cope_main_kernel,
                         cudaFuncAttributeMaxDynamicSharedMemorySize, SMEM_BYTES);

    cope_inv_kernel<<<NPOS, 256>>>(pos);
    cope_main_kernel<<<NBLOCKS, NTHREADS, SMEM_BYTES>>>(q, pos, out);
}